// round 15
// baseline (speedup 1.0000x reference)
#include <cuda_runtime.h>
#include <cuda_bf16.h>
#include <cstdint>

#define NB   16
#define NN   4096
#define NS   1024
#define NK   32
#define NC   64
#define NOUT 128
#define CIN  67          // 3 + 64

// kNN index scratch (static device global; allocation is forbidden)
__device__ int g_idx[NB * NS * NK];

// ---- packed f32x2 helpers (SIMD f32, .rn rounding == scalar f32 exactly) ----
__device__ __forceinline__ unsigned long long pk2(float lo, float hi) {
    unsigned long long r;
    asm("mov.b64 %0, {%1, %2};" : "=l"(r)
        : "r"(__float_as_uint(lo)), "r"(__float_as_uint(hi)));
    return r;
}
__device__ __forceinline__ void upk2(unsigned long long v, float& lo, float& hi) {
    unsigned a, b;
    asm("mov.b64 {%0, %1}, %2;" : "=r"(a), "=r"(b) : "l"(v));
    lo = __uint_as_float(a); hi = __uint_as_float(b);
}
#define F2ADD(o, a, b) asm("add.rn.f32x2 %0, %1, %2;" : "=l"(o) : "l"(a), "l"(b))
#define F2MUL(o, a, b) asm("mul.rn.f32x2 %0, %1, %2;" : "=l"(o) : "l"(a), "l"(b))
#define F2FMA(o, a, b, c) asm("fma.rn.f32x2 %0, %1, %2, %3;" : "=l"(o) : "l"(a), "l"(b), "l"(c))

// ---------------------------------------------------------------------------
// Stage 1: FPS. 1024 threads, 4 points/thread (2 f32x2 per dim).
// Same scheme as the measured-356us R8 kernel (single barrier/iter, pure
// REDUX two-stage argmax, parity double-buffered pairs) but with HALF the
// per-thread compute on the critical path (issue=57.8% @ occ 25% said
// issue-limited). pairs[] now 32 entries = exactly one REDUX-wide stage 2.
// ---------------------------------------------------------------------------
__global__ __launch_bounds__(1024, 1)
void fps_kernel(const float* __restrict__ xyz, float* __restrict__ new_xyz)
{
    extern __shared__ float sm[];
    float* xs = sm;
    float* ys = sm + NN;
    float* zs = sm + 2 * NN;
    __shared__ unsigned long long pairs[2][32];

    const int b   = blockIdx.x;
    const int tid = threadIdx.x;
    const int lane = tid & 31, wid = tid >> 5;

    const float* gx = xyz + (size_t)b * NN * 3;
    for (int j = tid; j < NN * 3; j += 1024) {
        float v = gx[j];
        int p = j / 3, c = j - p * 3;
        if (c == 0) xs[p] = v; else if (c == 1) ys[p] = v; else zs[p] = v;
    }
    __syncthreads();

    const int base = tid * 4;
    unsigned long long pxx[2], pyy[2], pzz[2];
    float dd[4];
#pragma unroll
    for (int p = 0; p < 2; p++) {
        pxx[p] = pk2(xs[base + 2 * p], xs[base + 2 * p + 1]);
        pyy[p] = pk2(ys[base + 2 * p], ys[base + 2 * p + 1]);
        pzz[p] = pk2(zs[base + 2 * p], zs[base + 2 * p + 1]);
        dd[2 * p] = 1e10f; dd[2 * p + 1] = 1e10f;
    }

    int far = 0;
    for (int it = 0; it < NS; it++) {
        const float cx = xs[far], cy = ys[far], cz = zs[far];
        if (tid == 0) {
            float* o = new_xyz + ((size_t)b * NS + it) * 3;
            o[0] = cx; o[1] = cy; o[2] = cz;
        }
        const unsigned long long ncx = pk2(-cx, -cx);
        const unsigned long long ncy = pk2(-cy, -cy);
        const unsigned long long ncz = pk2(-cz, -cz);

        float lm = 0.0f;
        int lidx = 0;
#pragma unroll
        for (int p = 0; p < 2; p++) {
            unsigned long long dx, dy, dz, t;
            F2ADD(dx, pxx[p], ncx);
            F2ADD(dy, pyy[p], ncy);
            F2ADD(dz, pzz[p], ncz);
            F2MUL(t, dx, dx);
            F2FMA(t, dy, dy, t);
            F2FMA(t, dz, dz, t);
            float d0, d1; upk2(t, d0, d1);
            float n0 = fminf(dd[2 * p], d0);
            float n1 = fminf(dd[2 * p + 1], d1);
            dd[2 * p] = n0; dd[2 * p + 1] = n1;
            if (n0 > lm) { lm = n0; lidx = base + 2 * p; }
            if (n1 > lm) { lm = n1; lidx = base + 2 * p + 1; }
        }
        const unsigned lmb = __float_as_uint(lm);
        const unsigned wm  = __reduce_max_sync(0xffffffffu, lmb);
        const unsigned wix = __reduce_min_sync(0xffffffffu,
                                (lmb == wm) ? (unsigned)lidx : 0xffffffffu);
        if (lane == 0)
            pairs[it & 1][wid] = ((unsigned long long)wm << 32) | (4095u - wix);
        __syncthreads();
        const unsigned long long kk = pairs[it & 1][lane];   // 32 warps = 32 slots
        const unsigned hi = (unsigned)(kk >> 32);
        const unsigned mh = __reduce_max_sync(0xffffffffu, hi);
        const unsigned lo = (hi == mh) ? (unsigned)kk : 0u;
        const unsigned ml = __reduce_max_sync(0xffffffffu, lo);
        far = 4095 - (int)ml;
    }
}

// ---------------------------------------------------------------------------
// Stage 2: kNN. (byte-identical to rounds 9/13/14 — 2-way split scan + merge)
// ---------------------------------------------------------------------------
#define HEAP_STRIDE 33
#define HALF 2048
__global__ __launch_bounds__(256, 1)
void knn_kernel(const float* __restrict__ xyz, const float* __restrict__ new_xyz)
{
    extern __shared__ float4 cand[];                       // NN entries = 64 KB
    unsigned long long* heap =
        (unsigned long long*)(cand + NN);                  // 256*33*8 = 67.6 KB

    const int b     = blockIdx.x >> 3;         // 8 blocks of 128 queries per batch
    const int chunk = blockIdx.x & 7;
    const int tid   = threadIdx.x;
    const int qloc  = tid & 127;               // query within chunk
    const int half  = tid >> 7;                // candidate half 0/1

    const float* gx = xyz + (size_t)b * NN * 3;
    for (int p = tid; p < NN; p += 256) {
        float x = gx[p * 3], y = gx[p * 3 + 1], z = gx[p * 3 + 2];
        float psq = __fadd_rn(__fadd_rn(__fmul_rn(x, x), __fmul_rn(y, y)),
                              __fmul_rn(z, z));
        cand[p] = make_float4(x, y, z, psq);
    }

    unsigned long long* hp = heap + tid * HEAP_STRIDE;
#pragma unroll
    for (int t = 0; t < NK; t++) hp[t] = ~0ull;
    unsigned long long root = ~0ull;
    __syncthreads();

    const int s = chunk * 128 + qloc;
    const float* q = new_xyz + ((size_t)b * NS + s) * 3;
    const float qx = q[0], qy = q[1], qz = q[2];
    const float qsq = __fadd_rn(__fadd_rn(__fmul_rn(qx, qx), __fmul_rn(qy, qy)),
                                __fmul_rn(qz, qz));

    const int start = half * HALF;
    float4 c = cand[start];
    for (int i = 0; i < HALF; i++) {
        float4 nxt = cand[start + ((i + 1) & (HALF - 1))];   // prefetch
        const int j = start + i;
        float dot = __fadd_rn(__fadd_rn(__fmul_rn(qx, c.x), __fmul_rn(qy, c.y)),
                              __fmul_rn(qz, c.z));
        float sq = __fsub_rn(__fadd_rn(qsq, c.w), __fmul_rn(2.0f, dot));
        unsigned ub = __float_as_uint(sq);
        ub ^= ((unsigned)((int)ub >> 31)) | 0x80000000u;   // order-preserving map
        unsigned long long key = ((unsigned long long)ub << 32) | (unsigned)j;

        if (key < root) {
            int pos = 0;
#pragma unroll
            for (int lvl = 0; lvl < 5; lvl++) {
                int ch = 2 * pos + 1;
                if (ch >= NK) break;
                unsigned long long lk = hp[ch];
                unsigned long long rk = (ch + 1 < NK) ? hp[ch + 1] : 0ull;
                unsigned long long mk = (rk > lk) ? rk : lk;
                int mc = (rk > lk) ? ch + 1 : ch;
                if (mk <= key) break;
                hp[pos] = mk;
                if (lvl == 0) root = mk;
                pos = mc;
            }
            hp[pos] = key;
            if (pos == 0) root = key;
        }
        c = nxt;
    }
    __syncthreads();

    // rank merge: my 32 keys vs partner's 32; unique keys -> ranks 0..63.
    const unsigned long long* hq = heap + (tid ^ 128) * HEAP_STRIDE;
    int* outp = g_idx + ((size_t)b * NS + s) * NK;
#pragma unroll 4
    for (int i = 0; i < NK; i++) {
        const unsigned long long k = hp[i];
        int r = 0;
#pragma unroll 8
        for (int t = 0; t < NK; t++) r += (hp[t] < k);
#pragma unroll 8
        for (int t = 0; t < NK; t++) r += (hq[t] < k);
        if (r < NK) outp[r] = (int)(k & 0xffffffffull);
    }
}

// ---------------------------------------------------------------------------
// Stage 3: gather + 1x1 conv (67->128) + max over K + LayerNorm.
// (byte-identical to round 14: fused single-pass LN, 4 barriers/query)
// ---------------------------------------------------------------------------
#define FT_PITCH 40
#define QPB3 32
__global__ __launch_bounds__(128, 4)
void embed_kernel(const float* __restrict__ xyz, const float* __restrict__ voxels,
                  const float* __restrict__ w, const float* __restrict__ bias,
                  const float* __restrict__ gamma, const float* __restrict__ beta,
                  const float* __restrict__ new_xyz, float* __restrict__ out)
{
    __shared__ float  wt[CIN * NOUT];        // [c][o]  34304 B
    __shared__ float  ft[CIN * FT_PITCH];    // [c][k]  10720 B
    __shared__ float  pm[4 * NOUT];          // [kg][o]  2048 B
    __shared__ float2 red[4];                //          32 B

    const int tid  = threadIdx.x;
    const int lane = tid & 31, wid = tid >> 5;
    const int og   = tid & 31;     // outch group: channels og*4..og*4+3
    const int kg   = tid >> 5;     // neighbor group: k = kg*8..kg*8+7
    const int k    = tid >> 2;     // gather: neighbor 0..31
    const int quad = tid & 3;      // gather: channel quarter

    {
        const float* wrow = w + tid * CIN;
        for (int c = 0; c < CIN; c++)
            wt[c * NOUT + tid] = wrow[c];
    }
    float bs[4];
#pragma unroll
    for (int j = 0; j < 4; j++) bs[j] = bias[og * 4 + j];
    const float go = gamma[tid], be = beta[tid];

    for (int q = 0; q < QPB3; q++) {
        const int gq = blockIdx.x * QPB3 + q;
        const int b  = gq >> 10;

        __syncthreads();   // WAR: previous iteration's readers are done

        const int nidx = g_idx[(size_t)gq * NK + k];
        const float4* vrow = (const float4*)(voxels + ((size_t)b * NN + nidx) * NC);
#pragma unroll
        for (int i = 0; i < 4; i++) {
            float4 v = vrow[quad * 4 + i];
            const int cb = 3 + quad * 16 + i * 4;
            ft[(cb + 0) * FT_PITCH + k] = v.x;
            ft[(cb + 1) * FT_PITCH + k] = v.y;
            ft[(cb + 2) * FT_PITCH + k] = v.z;
            ft[(cb + 3) * FT_PITCH + k] = v.w;
        }
        if (quad == 0) {
            const float* prow = xyz + ((size_t)b * NN + nidx) * 3;
            const float* qrow = new_xyz + (size_t)gq * 3;
            ft[0 * FT_PITCH + k] = __fsub_rn(prow[0], qrow[0]);
            ft[1 * FT_PITCH + k] = __fsub_rn(prow[1], qrow[1]);
            ft[2 * FT_PITCH + k] = __fsub_rn(prow[2], qrow[2]);
        }
        __syncthreads();   // ft ready

        float a0[8], a1[8], a2[8], a3[8];
#pragma unroll
        for (int n = 0; n < 8; n++) { a0[n] = bs[0]; a1[n] = bs[1]; a2[n] = bs[2]; a3[n] = bs[3]; }

#pragma unroll 2
        for (int c = 0; c < CIN; c++) {
            float4 wv = *(const float4*)&wt[c * NOUT + og * 4];
            float4 f0 = *(const float4*)&ft[c * FT_PITCH + kg * 8];
            float4 f1 = *(const float4*)&ft[c * FT_PITCH + kg * 8 + 4];
            float fv[8] = {f0.x, f0.y, f0.z, f0.w, f1.x, f1.y, f1.z, f1.w};
#pragma unroll
            for (int n = 0; n < 8; n++) {
                a0[n] = fmaf(wv.x, fv[n], a0[n]);
                a1[n] = fmaf(wv.y, fv[n], a1[n]);
                a2[n] = fmaf(wv.z, fv[n], a2[n]);
                a3[n] = fmaf(wv.w, fv[n], a3[n]);
            }
        }

        float p0 = a0[0], p1 = a1[0], p2 = a2[0], p3 = a3[0];
#pragma unroll
        for (int n = 1; n < 8; n++) {
            p0 = fmaxf(p0, a0[n]); p1 = fmaxf(p1, a1[n]);
            p2 = fmaxf(p2, a2[n]); p3 = fmaxf(p3, a3[n]);
        }
        *(float4*)&pm[kg * NOUT + og * 4] = make_float4(p0, p1, p2, p3);
        __syncthreads();   // pm ready

        // ---- max across neighbor groups + fused LN reduction ----
        const float m = fmaxf(fmaxf(pm[0 * NOUT + tid], pm[1 * NOUT + tid]),
                              fmaxf(pm[2 * NOUT + tid], pm[3 * NOUT + tid]));
        float s1 = m, s2 = m * m;
#pragma unroll
        for (int off = 16; off; off >>= 1) {
            s1 += __shfl_xor_sync(0xffffffffu, s1, off);
            s2 += __shfl_xor_sync(0xffffffffu, s2, off);
        }
        if (lane == 0) red[wid] = make_float2(s1, s2);
        __syncthreads();   // red ready

        const float mu  = (red[0].x + red[1].x + red[2].x + red[3].x) * (1.0f / 128.0f);
        const float ex2 = (red[0].y + red[1].y + red[2].y + red[3].y) * (1.0f / 128.0f);
        const float var = fmaxf(ex2 - mu * mu, 0.0f);
        out[(size_t)gq * NOUT + tid] = (m - mu) * rsqrtf(var + 1e-5f) * go + be;
    }
}

// ---------------------------------------------------------------------------
extern "C" void kernel_launch(void* const* d_in, const int* in_sizes, int n_in,
                              void* d_out, int out_size)
{
    const float* xyz    = (const float*)d_in[0];
    const float* voxels = (const float*)d_in[1];
    const float* conv_w = (const float*)d_in[2];
    const float* conv_b = (const float*)d_in[3];
    const float* ln_g   = (const float*)d_in[4];
    const float* ln_b   = (const float*)d_in[5];

    float* out      = (float*)d_out;                    // [B, S, OUT]
    float* new_xyz  = out + (size_t)NB * NS * NOUT;     // [B, S, 3]

    const size_t knn_smem = NN * sizeof(float4)
                          + 256 * HEAP_STRIDE * sizeof(unsigned long long);

    cudaFuncSetAttribute(fps_kernel, cudaFuncAttributeMaxDynamicSharedMemorySize,
                         3 * NN * sizeof(float));
    cudaFuncSetAttribute(knn_kernel, cudaFuncAttributeMaxDynamicSharedMemorySize,
                         (int)knn_smem);

    fps_kernel<<<NB, 1024, 3 * NN * sizeof(float)>>>(xyz, new_xyz);
    knn_kernel<<<NB * 8, 256, knn_smem>>>(xyz, new_xyz);
    embed_kernel<<<(NB * NS) / QPB3, 128>>>(xyz, voxels, conv_w, conv_b,
                                            ln_g, ln_b, new_xyz, out);
}

// round 16
// speedup vs baseline: 1.0304x; 1.0304x over previous
#include <cuda_runtime.h>
#include <cuda_bf16.h>
#include <cstdint>

#define NB   16
#define NN   4096
#define NS   1024
#define NK   32
#define NC   64
#define NOUT 128
#define CIN  67          // 3 + 64

// kNN index scratch (static device global; allocation is forbidden)
__device__ int g_idx[NB * NS * NK];

// ---- packed f32x2 helpers (SIMD f32, .rn rounding == scalar f32 exactly) ----
__device__ __forceinline__ unsigned long long pk2(float lo, float hi) {
    unsigned long long r;
    asm("mov.b64 %0, {%1, %2};" : "=l"(r)
        : "r"(__float_as_uint(lo)), "r"(__float_as_uint(hi)));
    return r;
}
__device__ __forceinline__ void upk2(unsigned long long v, float& lo, float& hi) {
    unsigned a, b;
    asm("mov.b64 {%0, %1}, %2;" : "=r"(a), "=r"(b) : "l"(v));
    lo = __uint_as_float(a); hi = __uint_as_float(b);
}
#define F2ADD(o, a, b) asm("add.rn.f32x2 %0, %1, %2;" : "=l"(o) : "l"(a), "l"(b))
#define F2MUL(o, a, b) asm("mul.rn.f32x2 %0, %1, %2;" : "=l"(o) : "l"(a), "l"(b))
#define F2FMA(o, a, b, c) asm("fma.rn.f32x2 %0, %1, %2, %3;" : "=l"(o) : "l"(a), "l"(b), "l"(c))

// ---------------------------------------------------------------------------
// Stage 1: FPS. (byte-identical to rounds 8/9/14: 356us measured; R15's
// 1024-thread variant regressed -> serial chain bound, structure frozen)
// ---------------------------------------------------------------------------
__global__ __launch_bounds__(512, 1)
void fps_kernel(const float* __restrict__ xyz, float* __restrict__ new_xyz)
{
    extern __shared__ float sm[];
    float* xs = sm;
    float* ys = sm + NN;
    float* zs = sm + 2 * NN;
    __shared__ unsigned long long pairs[2][16];

    const int b   = blockIdx.x;
    const int tid = threadIdx.x;
    const int lane = tid & 31, wid = tid >> 5;

    const float* gx = xyz + (size_t)b * NN * 3;
    for (int j = tid; j < NN * 3; j += 512) {
        float v = gx[j];
        int p = j / 3, c = j - p * 3;
        if (c == 0) xs[p] = v; else if (c == 1) ys[p] = v; else zs[p] = v;
    }
    __syncthreads();

    const int base = tid * 8;
    unsigned long long pxx[4], pyy[4], pzz[4];
    float dd[8];
#pragma unroll
    for (int p = 0; p < 4; p++) {
        pxx[p] = pk2(xs[base + 2 * p], xs[base + 2 * p + 1]);
        pyy[p] = pk2(ys[base + 2 * p], ys[base + 2 * p + 1]);
        pzz[p] = pk2(zs[base + 2 * p], zs[base + 2 * p + 1]);
        dd[2 * p] = 1e10f; dd[2 * p + 1] = 1e10f;
    }

    int far = 0;
    for (int it = 0; it < NS; it++) {
        const float cx = xs[far], cy = ys[far], cz = zs[far];
        if (tid == 0) {
            float* o = new_xyz + ((size_t)b * NS + it) * 3;
            o[0] = cx; o[1] = cy; o[2] = cz;
        }
        const unsigned long long ncx = pk2(-cx, -cx);
        const unsigned long long ncy = pk2(-cy, -cy);
        const unsigned long long ncz = pk2(-cz, -cz);

        float lm = 0.0f;
        int lidx = 0;
#pragma unroll
        for (int p = 0; p < 4; p++) {
            unsigned long long dx, dy, dz, t;
            F2ADD(dx, pxx[p], ncx);
            F2ADD(dy, pyy[p], ncy);
            F2ADD(dz, pzz[p], ncz);
            F2MUL(t, dx, dx);
            F2FMA(t, dy, dy, t);
            F2FMA(t, dz, dz, t);
            float d0, d1; upk2(t, d0, d1);
            float n0 = fminf(dd[2 * p], d0);
            float n1 = fminf(dd[2 * p + 1], d1);
            dd[2 * p] = n0; dd[2 * p + 1] = n1;
            if (n0 > lm) { lm = n0; lidx = base + 2 * p; }
            if (n1 > lm) { lm = n1; lidx = base + 2 * p + 1; }
        }
        const unsigned lmb = __float_as_uint(lm);
        const unsigned wm  = __reduce_max_sync(0xffffffffu, lmb);
        const unsigned wix = __reduce_min_sync(0xffffffffu,
                                (lmb == wm) ? (unsigned)lidx : 0xffffffffu);
        if (lane == 0)
            pairs[it & 1][wid] = ((unsigned long long)wm << 32) | (4095u - wix);
        __syncthreads();
        const unsigned long long kk = (lane < 16) ? pairs[it & 1][lane] : 0ull;
        const unsigned hi = (unsigned)(kk >> 32);
        const unsigned mh = __reduce_max_sync(0xffffffffu, hi);
        const unsigned lo = (hi == mh) ? (unsigned)kk : 0u;
        const unsigned ml = __reduce_max_sync(0xffffffffu, lo);
        far = 4095 - (int)ml;
    }
}

// ---------------------------------------------------------------------------
// Stage 2: kNN. (byte-identical to rounds 9/13/14 — 2-way split scan + merge)
// ---------------------------------------------------------------------------
#define HEAP_STRIDE 33
#define HALF 2048
__global__ __launch_bounds__(256, 1)
void knn_kernel(const float* __restrict__ xyz, const float* __restrict__ new_xyz)
{
    extern __shared__ float4 cand[];                       // NN entries = 64 KB
    unsigned long long* heap =
        (unsigned long long*)(cand + NN);                  // 256*33*8 = 67.6 KB

    const int b     = blockIdx.x >> 3;         // 8 blocks of 128 queries per batch
    const int chunk = blockIdx.x & 7;
    const int tid   = threadIdx.x;
    const int qloc  = tid & 127;               // query within chunk
    const int half  = tid >> 7;                // candidate half 0/1

    const float* gx = xyz + (size_t)b * NN * 3;
    for (int p = tid; p < NN; p += 256) {
        float x = gx[p * 3], y = gx[p * 3 + 1], z = gx[p * 3 + 2];
        float psq = __fadd_rn(__fadd_rn(__fmul_rn(x, x), __fmul_rn(y, y)),
                              __fmul_rn(z, z));
        cand[p] = make_float4(x, y, z, psq);
    }

    unsigned long long* hp = heap + tid * HEAP_STRIDE;
#pragma unroll
    for (int t = 0; t < NK; t++) hp[t] = ~0ull;
    unsigned long long root = ~0ull;
    __syncthreads();

    const int s = chunk * 128 + qloc;
    const float* q = new_xyz + ((size_t)b * NS + s) * 3;
    const float qx = q[0], qy = q[1], qz = q[2];
    const float qsq = __fadd_rn(__fadd_rn(__fmul_rn(qx, qx), __fmul_rn(qy, qy)),
                                __fmul_rn(qz, qz));

    const int start = half * HALF;
    float4 c = cand[start];
    for (int i = 0; i < HALF; i++) {
        float4 nxt = cand[start + ((i + 1) & (HALF - 1))];   // prefetch
        const int j = start + i;
        float dot = __fadd_rn(__fadd_rn(__fmul_rn(qx, c.x), __fmul_rn(qy, c.y)),
                              __fmul_rn(qz, c.z));
        float sq = __fsub_rn(__fadd_rn(qsq, c.w), __fmul_rn(2.0f, dot));
        unsigned ub = __float_as_uint(sq);
        ub ^= ((unsigned)((int)ub >> 31)) | 0x80000000u;   // order-preserving map
        unsigned long long key = ((unsigned long long)ub << 32) | (unsigned)j;

        if (key < root) {
            int pos = 0;
#pragma unroll
            for (int lvl = 0; lvl < 5; lvl++) {
                int ch = 2 * pos + 1;
                if (ch >= NK) break;
                unsigned long long lk = hp[ch];
                unsigned long long rk = (ch + 1 < NK) ? hp[ch + 1] : 0ull;
                unsigned long long mk = (rk > lk) ? rk : lk;
                int mc = (rk > lk) ? ch + 1 : ch;
                if (mk <= key) break;
                hp[pos] = mk;
                if (lvl == 0) root = mk;
                pos = mc;
            }
            hp[pos] = key;
            if (pos == 0) root = key;
        }
        c = nxt;
    }
    __syncthreads();

    // rank merge: my 32 keys vs partner's 32; unique keys -> ranks 0..63.
    const unsigned long long* hq = heap + (tid ^ 128) * HEAP_STRIDE;
    int* outp = g_idx + ((size_t)b * NS + s) * NK;
#pragma unroll 4
    for (int i = 0; i < NK; i++) {
        const unsigned long long k = hp[i];
        int r = 0;
#pragma unroll 8
        for (int t = 0; t < NK; t++) r += (hp[t] < k);
#pragma unroll 8
        for (int t = 0; t < NK; t++) r += (hq[t] < k);
        if (r < NK) outp[r] = (int)(k & 0xffffffffull);
    }
}

// ---------------------------------------------------------------------------
// Stage 3: gather + 1x1 conv (67->128) + max over K + LayerNorm.
// Same structure as R14 (fused single-pass LN) but the GEMM inner loop uses
// PACKED fma.rn.f32x2: each FFMA2 does 2 FMAs (neighbor pairs), targeting 2x
// FMA-pipe throughput. ft is neighbor-contiguous so ulonglong2 LDS.128 yields
// two neighbor-pairs with zero repack; weights broadcast via 4 mov.b64/step
// (ALU pipe, hidden). Rounding of fma.rn.f32x2 == scalar f32 exactly.
// ---------------------------------------------------------------------------
#define FT_PITCH 40
#define QPB3 32
__global__ __launch_bounds__(128, 4)
void embed_kernel(const float* __restrict__ xyz, const float* __restrict__ voxels,
                  const float* __restrict__ w, const float* __restrict__ bias,
                  const float* __restrict__ gamma, const float* __restrict__ beta,
                  const float* __restrict__ new_xyz, float* __restrict__ out)
{
    __shared__ float  wt[CIN * NOUT];        // [c][o]  34304 B
    __shared__ float  ft[CIN * FT_PITCH];    // [c][k]  10720 B
    __shared__ float  pm[4 * NOUT];          // [kg][o]  2048 B
    __shared__ float2 red[4];                //          32 B

    const int tid  = threadIdx.x;
    const int lane = tid & 31, wid = tid >> 5;
    const int og   = tid & 31;     // outch group: channels og*4..og*4+3
    const int kg   = tid >> 5;     // neighbor group: k = kg*8..kg*8+7
    const int k    = tid >> 2;     // gather: neighbor 0..31
    const int quad = tid & 3;      // gather: channel quarter

    {
        const float* wrow = w + tid * CIN;
        for (int c = 0; c < CIN; c++)
            wt[c * NOUT + tid] = wrow[c];
    }
    unsigned long long bp[4];      // packed (bias, bias) per outch
#pragma unroll
    for (int j = 0; j < 4; j++) {
        float bv = bias[og * 4 + j];
        bp[j] = pk2(bv, bv);
    }
    const float go = gamma[tid], be = beta[tid];

    for (int q = 0; q < QPB3; q++) {
        const int gq = blockIdx.x * QPB3 + q;
        const int b  = gq >> 10;

        __syncthreads();   // WAR: previous iteration's readers are done

        const int nidx = g_idx[(size_t)gq * NK + k];
        const float4* vrow = (const float4*)(voxels + ((size_t)b * NN + nidx) * NC);
#pragma unroll
        for (int i = 0; i < 4; i++) {
            float4 v = vrow[quad * 4 + i];
            const int cb = 3 + quad * 16 + i * 4;
            ft[(cb + 0) * FT_PITCH + k] = v.x;
            ft[(cb + 1) * FT_PITCH + k] = v.y;
            ft[(cb + 2) * FT_PITCH + k] = v.z;
            ft[(cb + 3) * FT_PITCH + k] = v.w;
        }
        if (quad == 0) {
            const float* prow = xyz + ((size_t)b * NN + nidx) * 3;
            const float* qrow = new_xyz + (size_t)gq * 3;
            ft[0 * FT_PITCH + k] = __fsub_rn(prow[0], qrow[0]);
            ft[1 * FT_PITCH + k] = __fsub_rn(prow[1], qrow[1]);
            ft[2 * FT_PITCH + k] = __fsub_rn(prow[2], qrow[2]);
        }
        __syncthreads();   // ft ready

        // ---- GEMM: 4 outch x 8 neighbors (4 f32x2 pairs) per thread ----
        unsigned long long acc[4][4];
#pragma unroll
        for (int o = 0; o < 4; o++)
#pragma unroll
            for (int p = 0; p < 4; p++) acc[o][p] = bp[o];

#pragma unroll 2
        for (int c = 0; c < CIN; c++) {
            float4 wv = *(const float4*)&wt[c * NOUT + og * 4];
            unsigned long long w0 = pk2(wv.x, wv.x);
            unsigned long long w1 = pk2(wv.y, wv.y);
            unsigned long long w2 = pk2(wv.z, wv.z);
            unsigned long long w3 = pk2(wv.w, wv.w);
            ulonglong2 fa = *(const ulonglong2*)&ft[c * FT_PITCH + kg * 8];
            ulonglong2 fb = *(const ulonglong2*)&ft[c * FT_PITCH + kg * 8 + 4];
            unsigned long long f0 = fa.x, f1 = fa.y, f2 = fb.x, f3 = fb.y;
            F2FMA(acc[0][0], w0, f0, acc[0][0]);
            F2FMA(acc[1][0], w1, f0, acc[1][0]);
            F2FMA(acc[2][0], w2, f0, acc[2][0]);
            F2FMA(acc[3][0], w3, f0, acc[3][0]);
            F2FMA(acc[0][1], w0, f1, acc[0][1]);
            F2FMA(acc[1][1], w1, f1, acc[1][1]);
            F2FMA(acc[2][1], w2, f1, acc[2][1]);
            F2FMA(acc[3][1], w3, f1, acc[3][1]);
            F2FMA(acc[0][2], w0, f2, acc[0][2]);
            F2FMA(acc[1][2], w1, f2, acc[1][2]);
            F2FMA(acc[2][2], w2, f2, acc[2][2]);
            F2FMA(acc[3][2], w3, f2, acc[3][2]);
            F2FMA(acc[0][3], w0, f3, acc[0][3]);
            F2FMA(acc[1][3], w1, f3, acc[1][3]);
            F2FMA(acc[2][3], w2, f3, acc[2][3]);
            F2FMA(acc[3][3], w3, f3, acc[3][3]);
        }

        // partial max over this thread's 8 neighbors per outch
        float pmax[4];
#pragma unroll
        for (int o = 0; o < 4; o++) {
            float lo, hi; upk2(acc[o][0], lo, hi);
            float m = fmaxf(lo, hi);
#pragma unroll
            for (int p = 1; p < 4; p++) {
                upk2(acc[o][p], lo, hi);
                m = fmaxf(m, fmaxf(lo, hi));
            }
            pmax[o] = m;
        }
        *(float4*)&pm[kg * NOUT + og * 4] =
            make_float4(pmax[0], pmax[1], pmax[2], pmax[3]);
        __syncthreads();   // pm ready

        // ---- max across neighbor groups + fused LN reduction ----
        const float m = fmaxf(fmaxf(pm[0 * NOUT + tid], pm[1 * NOUT + tid]),
                              fmaxf(pm[2 * NOUT + tid], pm[3 * NOUT + tid]));
        float s1 = m, s2 = m * m;
#pragma unroll
        for (int off = 16; off; off >>= 1) {
            s1 += __shfl_xor_sync(0xffffffffu, s1, off);
            s2 += __shfl_xor_sync(0xffffffffu, s2, off);
        }
        if (lane == 0) red[wid] = make_float2(s1, s2);
        __syncthreads();   // red ready

        const float mu  = (red[0].x + red[1].x + red[2].x + red[3].x) * (1.0f / 128.0f);
        const float ex2 = (red[0].y + red[1].y + red[2].y + red[3].y) * (1.0f / 128.0f);
        const float var = fmaxf(ex2 - mu * mu, 0.0f);
        out[(size_t)gq * NOUT + tid] = (m - mu) * rsqrtf(var + 1e-5f) * go + be;
    }
}

// ---------------------------------------------------------------------------
extern "C" void kernel_launch(void* const* d_in, const int* in_sizes, int n_in,
                              void* d_out, int out_size)
{
    const float* xyz    = (const float*)d_in[0];
    const float* voxels = (const float*)d_in[1];
    const float* conv_w = (const float*)d_in[2];
    const float* conv_b = (const float*)d_in[3];
    const float* ln_g   = (const float*)d_in[4];
    const float* ln_b   = (const float*)d_in[5];

    float* out      = (float*)d_out;                    // [B, S, OUT]
    float* new_xyz  = out + (size_t)NB * NS * NOUT;     // [B, S, 3]

    const size_t knn_smem = NN * sizeof(float4)
                          + 256 * HEAP_STRIDE * sizeof(unsigned long long);

    cudaFuncSetAttribute(fps_kernel, cudaFuncAttributeMaxDynamicSharedMemorySize,
                         3 * NN * sizeof(float));
    cudaFuncSetAttribute(knn_kernel, cudaFuncAttributeMaxDynamicSharedMemorySize,
                         (int)knn_smem);

    fps_kernel<<<NB, 512, 3 * NN * sizeof(float)>>>(xyz, new_xyz);
    knn_kernel<<<NB * 8, 256, knn_smem>>>(xyz, new_xyz);
    embed_kernel<<<(NB * NS) / QPB3, 128>>>(xyz, voxels, conv_w, conv_b,
                                            ln_g, ln_b, new_xyz, out);
}

// round 17
// speedup vs baseline: 1.0840x; 1.0521x over previous
#include <cuda_runtime.h>
#include <cuda_bf16.h>
#include <cstdint>

#define NB   16
#define NN   4096
#define NS   1024
#define NK   32
#define NC   64
#define NOUT 128
#define CIN  67          // 3 + 64

// kNN index scratch (static device global; allocation is forbidden)
__device__ int g_idx[NB * NS * NK];
// embed work-stealing counter (reset per launch via cudaMemsetAsync node)
__device__ unsigned int g_unit_ctr;

// ---- packed f32x2 helpers (SIMD f32, .rn rounding == scalar f32 exactly) ----
__device__ __forceinline__ unsigned long long pk2(float lo, float hi) {
    unsigned long long r;
    asm("mov.b64 %0, {%1, %2};" : "=l"(r)
        : "r"(__float_as_uint(lo)), "r"(__float_as_uint(hi)));
    return r;
}
__device__ __forceinline__ void upk2(unsigned long long v, float& lo, float& hi) {
    unsigned a, b;
    asm("mov.b64 {%0, %1}, %2;" : "=r"(a), "=r"(b) : "l"(v));
    lo = __uint_as_float(a); hi = __uint_as_float(b);
}
#define F2ADD(o, a, b) asm("add.rn.f32x2 %0, %1, %2;" : "=l"(o) : "l"(a), "l"(b))
#define F2MUL(o, a, b) asm("mul.rn.f32x2 %0, %1, %2;" : "=l"(o) : "l"(a), "l"(b))
#define F2FMA(o, a, b, c) asm("fma.rn.f32x2 %0, %1, %2, %3;" : "=l"(o) : "l"(a), "l"(b), "l"(c))

// ---------------------------------------------------------------------------
// Stage 1: FPS. (byte-identical to rounds 8/9/14/16: 356us measured, frozen)
// ---------------------------------------------------------------------------
__global__ __launch_bounds__(512, 1)
void fps_kernel(const float* __restrict__ xyz, float* __restrict__ new_xyz)
{
    extern __shared__ float sm[];
    float* xs = sm;
    float* ys = sm + NN;
    float* zs = sm + 2 * NN;
    __shared__ unsigned long long pairs[2][16];

    const int b   = blockIdx.x;
    const int tid = threadIdx.x;
    const int lane = tid & 31, wid = tid >> 5;

    const float* gx = xyz + (size_t)b * NN * 3;
    for (int j = tid; j < NN * 3; j += 512) {
        float v = gx[j];
        int p = j / 3, c = j - p * 3;
        if (c == 0) xs[p] = v; else if (c == 1) ys[p] = v; else zs[p] = v;
    }
    __syncthreads();

    const int base = tid * 8;
    unsigned long long pxx[4], pyy[4], pzz[4];
    float dd[8];
#pragma unroll
    for (int p = 0; p < 4; p++) {
        pxx[p] = pk2(xs[base + 2 * p], xs[base + 2 * p + 1]);
        pyy[p] = pk2(ys[base + 2 * p], ys[base + 2 * p + 1]);
        pzz[p] = pk2(zs[base + 2 * p], zs[base + 2 * p + 1]);
        dd[2 * p] = 1e10f; dd[2 * p + 1] = 1e10f;
    }

    int far = 0;
    for (int it = 0; it < NS; it++) {
        const float cx = xs[far], cy = ys[far], cz = zs[far];
        if (tid == 0) {
            float* o = new_xyz + ((size_t)b * NS + it) * 3;
            o[0] = cx; o[1] = cy; o[2] = cz;
        }
        const unsigned long long ncx = pk2(-cx, -cx);
        const unsigned long long ncy = pk2(-cy, -cy);
        const unsigned long long ncz = pk2(-cz, -cz);

        float lm = 0.0f;
        int lidx = 0;
#pragma unroll
        for (int p = 0; p < 4; p++) {
            unsigned long long dx, dy, dz, t;
            F2ADD(dx, pxx[p], ncx);
            F2ADD(dy, pyy[p], ncy);
            F2ADD(dz, pzz[p], ncz);
            F2MUL(t, dx, dx);
            F2FMA(t, dy, dy, t);
            F2FMA(t, dz, dz, t);
            float d0, d1; upk2(t, d0, d1);
            float n0 = fminf(dd[2 * p], d0);
            float n1 = fminf(dd[2 * p + 1], d1);
            dd[2 * p] = n0; dd[2 * p + 1] = n1;
            if (n0 > lm) { lm = n0; lidx = base + 2 * p; }
            if (n1 > lm) { lm = n1; lidx = base + 2 * p + 1; }
        }
        const unsigned lmb = __float_as_uint(lm);
        const unsigned wm  = __reduce_max_sync(0xffffffffu, lmb);
        const unsigned wix = __reduce_min_sync(0xffffffffu,
                                (lmb == wm) ? (unsigned)lidx : 0xffffffffu);
        if (lane == 0)
            pairs[it & 1][wid] = ((unsigned long long)wm << 32) | (4095u - wix);
        __syncthreads();
        const unsigned long long kk = (lane < 16) ? pairs[it & 1][lane] : 0ull;
        const unsigned hi = (unsigned)(kk >> 32);
        const unsigned mh = __reduce_max_sync(0xffffffffu, hi);
        const unsigned lo = (hi == mh) ? (unsigned)kk : 0u;
        const unsigned ml = __reduce_max_sync(0xffffffffu, lo);
        far = 4095 - (int)ml;
    }
}

// ---------------------------------------------------------------------------
// Stage 2: kNN. (byte-identical to rounds 9/13/14/16)
// ---------------------------------------------------------------------------
#define HEAP_STRIDE 33
#define HALF 2048
__global__ __launch_bounds__(256, 1)
void knn_kernel(const float* __restrict__ xyz, const float* __restrict__ new_xyz)
{
    extern __shared__ float4 cand[];                       // NN entries = 64 KB
    unsigned long long* heap =
        (unsigned long long*)(cand + NN);                  // 256*33*8 = 67.6 KB

    const int b     = blockIdx.x >> 3;         // 8 blocks of 128 queries per batch
    const int chunk = blockIdx.x & 7;
    const int tid   = threadIdx.x;
    const int qloc  = tid & 127;               // query within chunk
    const int half  = tid >> 7;                // candidate half 0/1

    const float* gx = xyz + (size_t)b * NN * 3;
    for (int p = tid; p < NN; p += 256) {
        float x = gx[p * 3], y = gx[p * 3 + 1], z = gx[p * 3 + 2];
        float psq = __fadd_rn(__fadd_rn(__fmul_rn(x, x), __fmul_rn(y, y)),
                              __fmul_rn(z, z));
        cand[p] = make_float4(x, y, z, psq);
    }

    unsigned long long* hp = heap + tid * HEAP_STRIDE;
#pragma unroll
    for (int t = 0; t < NK; t++) hp[t] = ~0ull;
    unsigned long long root = ~0ull;
    __syncthreads();

    const int s = chunk * 128 + qloc;
    const float* q = new_xyz + ((size_t)b * NS + s) * 3;
    const float qx = q[0], qy = q[1], qz = q[2];
    const float qsq = __fadd_rn(__fadd_rn(__fmul_rn(qx, qx), __fmul_rn(qy, qy)),
                                __fmul_rn(qz, qz));

    const int start = half * HALF;
    float4 c = cand[start];
    for (int i = 0; i < HALF; i++) {
        float4 nxt = cand[start + ((i + 1) & (HALF - 1))];   // prefetch
        const int j = start + i;
        float dot = __fadd_rn(__fadd_rn(__fmul_rn(qx, c.x), __fmul_rn(qy, c.y)),
                              __fmul_rn(qz, c.z));
        float sq = __fsub_rn(__fadd_rn(qsq, c.w), __fmul_rn(2.0f, dot));
        unsigned ub = __float_as_uint(sq);
        ub ^= ((unsigned)((int)ub >> 31)) | 0x80000000u;   // order-preserving map
        unsigned long long key = ((unsigned long long)ub << 32) | (unsigned)j;

        if (key < root) {
            int pos = 0;
#pragma unroll
            for (int lvl = 0; lvl < 5; lvl++) {
                int ch = 2 * pos + 1;
                if (ch >= NK) break;
                unsigned long long lk = hp[ch];
                unsigned long long rk = (ch + 1 < NK) ? hp[ch + 1] : 0ull;
                unsigned long long mk = (rk > lk) ? rk : lk;
                int mc = (rk > lk) ? ch + 1 : ch;
                if (mk <= key) break;
                hp[pos] = mk;
                if (lvl == 0) root = mk;
                pos = mc;
            }
            hp[pos] = key;
            if (pos == 0) root = key;
        }
        c = nxt;
    }
    __syncthreads();

    // rank merge: my 32 keys vs partner's 32; unique keys -> ranks 0..63.
    const unsigned long long* hq = heap + (tid ^ 128) * HEAP_STRIDE;
    int* outp = g_idx + ((size_t)b * NS + s) * NK;
#pragma unroll 4
    for (int i = 0; i < NK; i++) {
        const unsigned long long k = hp[i];
        int r = 0;
#pragma unroll 8
        for (int t = 0; t < NK; t++) r += (hp[t] < k);
#pragma unroll 8
        for (int t = 0; t < NK; t++) r += (hq[t] < k);
        if (r < NK) outp[r] = (int)(k & 0xffffffffull);
    }
}

// ---------------------------------------------------------------------------
// Stage 3: gather + 1x1 conv + max + LN. Per-query body identical to R16.
// NEW: atomic work-stealing over 2048 units of 8 queries, grid = 148*4 = 592
// blocks (exactly one full wave at occupancy 4). Removes the 4-vs-3.46
// resident-block imbalance: every SM now does ~total/148 work.
// ---------------------------------------------------------------------------
#define FT_PITCH 40
#define UNIT_Q   8
#define N_UNITS  ((NB * NS) / UNIT_Q)          // 2048
__global__ __launch_bounds__(128, 4)
void embed_kernel(const float* __restrict__ xyz, const float* __restrict__ voxels,
                  const float* __restrict__ w, const float* __restrict__ bias,
                  const float* __restrict__ gamma, const float* __restrict__ beta,
                  const float* __restrict__ new_xyz, float* __restrict__ out)
{
    __shared__ float  wt[CIN * NOUT];        // [c][o]  34304 B
    __shared__ float  ft[CIN * FT_PITCH];    // [c][k]  10720 B
    __shared__ float  pm[4 * NOUT];          // [kg][o]  2048 B
    __shared__ float2 red[4];                //          32 B
    __shared__ unsigned s_unit;

    const int tid  = threadIdx.x;
    const int lane = tid & 31, wid = tid >> 5;
    const int og   = tid & 31;     // outch group: channels og*4..og*4+3
    const int kg   = tid >> 5;     // neighbor group: k = kg*8..kg*8+7
    const int k    = tid >> 2;     // gather: neighbor 0..31
    const int quad = tid & 3;      // gather: channel quarter

    {
        const float* wrow = w + tid * CIN;
        for (int c = 0; c < CIN; c++)
            wt[c * NOUT + tid] = wrow[c];
    }
    unsigned long long bp[4];      // packed (bias, bias) per outch
#pragma unroll
    for (int j = 0; j < 4; j++) {
        float bv = bias[og * 4 + j];
        bp[j] = pk2(bv, bv);
    }
    const float go = gamma[tid], be = beta[tid];

    for (;;) {
        if (tid == 0) s_unit = atomicAdd(&g_unit_ctr, 1u);
        __syncthreads();                 // s_unit visible (also WAR for smem)
        const unsigned u = s_unit;
        if (u >= N_UNITS) break;

        for (int qi = 0; qi < UNIT_Q; qi++) {
            const int gq = (int)u * UNIT_Q + qi;
            const int b  = gq >> 10;

            const int nidx = g_idx[(size_t)gq * NK + k];
            const float4* vrow = (const float4*)(voxels + ((size_t)b * NN + nidx) * NC);
#pragma unroll
            for (int i = 0; i < 4; i++) {
                float4 v = vrow[quad * 4 + i];
                const int cb = 3 + quad * 16 + i * 4;
                ft[(cb + 0) * FT_PITCH + k] = v.x;
                ft[(cb + 1) * FT_PITCH + k] = v.y;
                ft[(cb + 2) * FT_PITCH + k] = v.z;
                ft[(cb + 3) * FT_PITCH + k] = v.w;
            }
            if (quad == 0) {
                const float* prow = xyz + ((size_t)b * NN + nidx) * 3;
                const float* qrow = new_xyz + (size_t)gq * 3;
                ft[0 * FT_PITCH + k] = __fsub_rn(prow[0], qrow[0]);
                ft[1 * FT_PITCH + k] = __fsub_rn(prow[1], qrow[1]);
                ft[2 * FT_PITCH + k] = __fsub_rn(prow[2], qrow[2]);
            }
            __syncthreads();   // ft ready

            // ---- GEMM: 4 outch x 8 neighbors (4 f32x2 pairs) per thread ----
            unsigned long long acc[4][4];
#pragma unroll
            for (int o = 0; o < 4; o++)
#pragma unroll
                for (int p = 0; p < 4; p++) acc[o][p] = bp[o];

#pragma unroll 2
            for (int c = 0; c < CIN; c++) {
                float4 wv = *(const float4*)&wt[c * NOUT + og * 4];
                unsigned long long w0 = pk2(wv.x, wv.x);
                unsigned long long w1 = pk2(wv.y, wv.y);
                unsigned long long w2 = pk2(wv.z, wv.z);
                unsigned long long w3 = pk2(wv.w, wv.w);
                ulonglong2 fa = *(const ulonglong2*)&ft[c * FT_PITCH + kg * 8];
                ulonglong2 fb = *(const ulonglong2*)&ft[c * FT_PITCH + kg * 8 + 4];
                unsigned long long f0 = fa.x, f1 = fa.y, f2 = fb.x, f3 = fb.y;
                F2FMA(acc[0][0], w0, f0, acc[0][0]);
                F2FMA(acc[1][0], w1, f0, acc[1][0]);
                F2FMA(acc[2][0], w2, f0, acc[2][0]);
                F2FMA(acc[3][0], w3, f0, acc[3][0]);
                F2FMA(acc[0][1], w0, f1, acc[0][1]);
                F2FMA(acc[1][1], w1, f1, acc[1][1]);
                F2FMA(acc[2][1], w2, f1, acc[2][1]);
                F2FMA(acc[3][1], w3, f1, acc[3][1]);
                F2FMA(acc[0][2], w0, f2, acc[0][2]);
                F2FMA(acc[1][2], w1, f2, acc[1][2]);
                F2FMA(acc[2][2], w2, f2, acc[2][2]);
                F2FMA(acc[3][2], w3, f2, acc[3][2]);
                F2FMA(acc[0][3], w0, f3, acc[0][3]);
                F2FMA(acc[1][3], w1, f3, acc[1][3]);
                F2FMA(acc[2][3], w2, f3, acc[2][3]);
                F2FMA(acc[3][3], w3, f3, acc[3][3]);
            }

            float pmax[4];
#pragma unroll
            for (int o = 0; o < 4; o++) {
                float lo, hi; upk2(acc[o][0], lo, hi);
                float m = fmaxf(lo, hi);
#pragma unroll
                for (int p = 1; p < 4; p++) {
                    upk2(acc[o][p], lo, hi);
                    m = fmaxf(m, fmaxf(lo, hi));
                }
                pmax[o] = m;
            }
            *(float4*)&pm[kg * NOUT + og * 4] =
                make_float4(pmax[0], pmax[1], pmax[2], pmax[3]);
            __syncthreads();   // pm ready

            const float m = fmaxf(fmaxf(pm[0 * NOUT + tid], pm[1 * NOUT + tid]),
                                  fmaxf(pm[2 * NOUT + tid], pm[3 * NOUT + tid]));
            float s1 = m, s2 = m * m;
#pragma unroll
            for (int off = 16; off; off >>= 1) {
                s1 += __shfl_xor_sync(0xffffffffu, s1, off);
                s2 += __shfl_xor_sync(0xffffffffu, s2, off);
            }
            if (lane == 0) red[wid] = make_float2(s1, s2);
            __syncthreads();   // red ready

            const float mu  = (red[0].x + red[1].x + red[2].x + red[3].x) * (1.0f / 128.0f);
            const float ex2 = (red[0].y + red[1].y + red[2].y + red[3].y) * (1.0f / 128.0f);
            const float var = fmaxf(ex2 - mu * mu, 0.0f);
            out[(size_t)gq * NOUT + tid] = (m - mu) * rsqrtf(var + 1e-5f) * go + be;
            __syncthreads();   // WAR before next query's gather
        }
    }
}

// ---------------------------------------------------------------------------
extern "C" void kernel_launch(void* const* d_in, const int* in_sizes, int n_in,
                              void* d_out, int out_size)
{
    const float* xyz    = (const float*)d_in[0];
    const float* voxels = (const float*)d_in[1];
    const float* conv_w = (const float*)d_in[2];
    const float* conv_b = (const float*)d_in[3];
    const float* ln_g   = (const float*)d_in[4];
    const float* ln_b   = (const float*)d_in[5];

    float* out      = (float*)d_out;                    // [B, S, OUT]
    float* new_xyz  = out + (size_t)NB * NS * NOUT;     // [B, S, 3]

    const size_t knn_smem = NN * sizeof(float4)
                          + 256 * HEAP_STRIDE * sizeof(unsigned long long);

    cudaFuncSetAttribute(fps_kernel, cudaFuncAttributeMaxDynamicSharedMemorySize,
                         3 * NN * sizeof(float));
    cudaFuncSetAttribute(knn_kernel, cudaFuncAttributeMaxDynamicSharedMemorySize,
                         (int)knn_smem);

    // reset work-stealing counter (memset node: graph-capturable, no alloc)
    void* ctr_addr = nullptr;
    cudaGetSymbolAddress(&ctr_addr, g_unit_ctr);

    fps_kernel<<<NB, 512, 3 * NN * sizeof(float)>>>(xyz, new_xyz);
    knn_kernel<<<NB * 8, 256, knn_smem>>>(xyz, new_xyz);
    cudaMemsetAsync(ctr_addr, 0, sizeof(unsigned int), 0);
    embed_kernel<<<148 * 4, 128>>>(xyz, voxels, conv_w, conv_b,
                                   ln_g, ln_b, new_xyz, out);
}